// round 10
// baseline (speedup 1.0000x reference)
#include <cuda_runtime.h>

#define N_NODES 100000
#define N_EDGES 1600000
#define F 128
#define TPAD 132                 // T row stride (pad kills 2-way bank conflict)
#define TILE_ROWS 64
#define NTILES ((N_NODES + TILE_ROWS - 1) / TILE_ROWS)   // 1563
#define LAYER_GRID 148
#define LAYER_THREADS 512

// smem: W(128*128) + bias(128) + T double buffer (2 * 64 * 132)
#define SMEM_FLOATS (F * F + F + 2 * TILE_ROWS * TPAD)
#define SMEM_BYTES (SMEM_FLOATS * 4)   // 133632 B

#define BAR_SYNC(id)   asm volatile("bar.sync %0, 512;"   :: "r"(id) : "memory")
#define BAR_ARRIVE(id) asm volatile("bar.arrive %0, 512;" :: "r"(id) : "memory")

// ---------------- scratch (no allocations allowed) ----------------
__device__ int   g_counts[N_NODES];
__device__ int   g_off[N_NODES + 1];
__device__ int   g_cursor[N_NODES];
__device__ float g_inv[N_NODES];
__device__ int   g_csr[N_EDGES];
__device__ float g_h0[(size_t)N_NODES * F];
__device__ float g_h1[(size_t)N_NODES * F];

// ---------------- preprocessing: build CSR by dst (3 launches) ----------------
__global__ void k_hist(const int* __restrict__ dst) {
    int e = blockIdx.x * blockDim.x + threadIdx.x;
    if (e < N_EDGES) atomicAdd(&g_counts[dst[e]], 1);
}

__global__ void k_scan1() {
    __shared__ int wsum[32];
    __shared__ int base_sh;
    int tid = threadIdx.x;
    int lane = tid & 31;
    int wid = tid >> 5;
    if (tid == 0) base_sh = 0;
    __syncthreads();

    for (int base = 0; base < N_NODES; base += 4096) {
        int i = base + tid * 4;
        int4 v = make_int4(0, 0, 0, 0);
        if (i < N_NODES) v = *(const int4*)(g_counts + i);
        int s = v.x + v.y + v.z + v.w;

        int incl = s;
        #pragma unroll
        for (int d = 1; d < 32; d <<= 1) {
            int x = __shfl_up_sync(0xffffffffu, incl, d);
            if (lane >= d) incl += x;
        }
        if (lane == 31) wsum[wid] = incl;
        __syncthreads();

        if (wid == 0) {
            int ws = wsum[lane];
            int wincl = ws;
            #pragma unroll
            for (int d = 1; d < 32; d <<= 1) {
                int x = __shfl_up_sync(0xffffffffu, wincl, d);
                if (lane >= d) wincl += x;
            }
            wsum[lane] = wincl - ws;
        }
        __syncthreads();

        int chunk_base = base_sh;
        int pre = chunk_base + wsum[wid] + (incl - s);
        if (i < N_NODES) {
            int e0 = pre;
            int e1 = e0 + v.x;
            int e2 = e1 + v.y;
            int e3 = e2 + v.z;
            *(int4*)(g_off + i)    = make_int4(e0, e1, e2, e3);
            *(int4*)(g_cursor + i) = make_int4(e0, e1, e2, e3);
            g_inv[i + 0] = 1.0f / (float)(v.x > 0 ? v.x : 1);
            g_inv[i + 1] = 1.0f / (float)(v.y > 0 ? v.y : 1);
            g_inv[i + 2] = 1.0f / (float)(v.z > 0 ? v.z : 1);
            g_inv[i + 3] = 1.0f / (float)(v.w > 0 ? v.w : 1);
        }
        __syncthreads();
        if (tid == 1023) base_sh = chunk_base + wsum[31] + incl;
        __syncthreads();
    }
    if (tid == 0) g_off[N_NODES] = base_sh;
}

__global__ void k_scatter(const int* __restrict__ src, const int* __restrict__ dst) {
    int i = blockIdx.x * blockDim.x + threadIdx.x;
    if (i < N_EDGES) {
        int d = dst[i];
        int pos = atomicAdd(&g_cursor[d], 1);
        g_csr[pos] = src[i];
    }
    if (i < N_NODES) g_counts[i] = 0;   // re-zero for next invocation
}

// ---------------- fused layer: warp-specialized producer/consumer ----------------
// Warps 0-7: gather/aggregate 64-row tiles into smem T (double buffered).
// Warps 8-15: register-tiled GEMM (thread = 4 rows x 8 cols) + bias + relu + store.
// Handoff: named barriers. full = 1+b, empty = 3+b.
__global__ __launch_bounds__(LAYER_THREADS, 1)
void k_layer(const float* __restrict__ hin, const float* __restrict__ Wg,
             const float* __restrict__ bias, float* __restrict__ hout,
             int do_relu) {
    extern __shared__ float smem[];
    float* sW = smem;                 // F*F
    float* sb = smem + F * F;         // F
    float* sT = sb + F;               // 2 * TILE_ROWS * TPAD

    int tid = threadIdx.x;
    for (int i = tid; i < (F * F) / 4; i += LAYER_THREADS)
        ((float4*)sW)[i] = ((const float4*)Wg)[i];
    if (tid < F) sb[tid] = bias[tid];
    __syncthreads();

    int lane = tid & 31;
    int wId = tid >> 5;

    if (wId < 8) {
        // ================= producers =================
        int li = 0;
        for (int t = blockIdx.x; t < NTILES; t += gridDim.x, ++li) {
            int b = li & 1;
            float* Tb = sT + b * (TILE_ROWS * TPAD);
            if (li >= 2) BAR_SYNC(3 + b);          // wait buffer empty

            int lrow0 = wId * 8;
            int row0 = t * TILE_ROWS + lrow0;
            #pragma unroll 1
            for (int r = 0; r < 8; ++r) {
                int row = row0 + r;
                float4 tv = make_float4(0.f, 0.f, 0.f, 0.f);
                if (row < N_NODES) {
                    int e = g_off[row];
                    int e1 = g_off[row + 1];
                    float4 acc = make_float4(0.f, 0.f, 0.f, 0.f);
                    for (; e + 4 <= e1; e += 4) {
                        int s0 = g_csr[e + 0], s1 = g_csr[e + 1];
                        int s2 = g_csr[e + 2], s3 = g_csr[e + 3];
                        float4 v0 = *(const float4*)(hin + (size_t)s0 * F + lane * 4);
                        float4 v1 = *(const float4*)(hin + (size_t)s1 * F + lane * 4);
                        float4 v2 = *(const float4*)(hin + (size_t)s2 * F + lane * 4);
                        float4 v3 = *(const float4*)(hin + (size_t)s3 * F + lane * 4);
                        acc.x += (v0.x + v1.x) + (v2.x + v3.x);
                        acc.y += (v0.y + v1.y) + (v2.y + v3.y);
                        acc.z += (v0.z + v1.z) + (v2.z + v3.z);
                        acc.w += (v0.w + v1.w) + (v2.w + v3.w);
                    }
                    for (; e < e1; ++e) {
                        int s = g_csr[e];
                        float4 v = *(const float4*)(hin + (size_t)s * F + lane * 4);
                        acc.x += v.x; acc.y += v.y; acc.z += v.z; acc.w += v.w;
                    }
                    float sc = g_inv[row];
                    float4 hv = *(const float4*)(hin + (size_t)row * F + lane * 4);
                    tv.x = fmaf(acc.x, sc, hv.x);
                    tv.y = fmaf(acc.y, sc, hv.y);
                    tv.z = fmaf(acc.z, sc, hv.z);
                    tv.w = fmaf(acc.w, sc, hv.w);
                }
                *(float4*)(Tb + (lrow0 + r) * TPAD + lane * 4) = tv;
            }
            __threadfence_block();
            BAR_ARRIVE(1 + b);                      // signal full
        }
    } else {
        // ================= consumers =================
        int ct = tid - 256;
        int ri = ct >> 4;        // 0..15 -> rows ri*4..+3
        int ci = ct & 15;        // 0..15 -> cols ci*8..+7
        float4 bc0 = *(const float4*)(sb + ci * 8);
        float4 bc1 = *(const float4*)(sb + ci * 8 + 4);
        const float* WC = sW + ci * 8;

        int li = 0;
        for (int t = blockIdx.x; t < NTILES; t += gridDim.x, ++li) {
            int b = li & 1;
            const float* Tb = sT + b * (TILE_ROWS * TPAD);
            BAR_SYNC(1 + b);                        // wait buffer full

            float4 a0c[4], a1c[4];
            #pragma unroll
            for (int r = 0; r < 4; ++r) { a0c[r] = bc0; a1c[r] = bc1; }

            const float* Trow = Tb + (ri * 4) * TPAD;
            #pragma unroll 1
            for (int kk = 0; kk < F / 4; ++kk) {
                float4 a0 = *(const float4*)(Trow + 0 * TPAD + 4 * kk);
                float4 a1 = *(const float4*)(Trow + 1 * TPAD + 4 * kk);
                float4 a2 = *(const float4*)(Trow + 2 * TPAD + 4 * kk);
                float4 a3 = *(const float4*)(Trow + 3 * TPAD + 4 * kk);
                const float* Wr = WC + (4 * kk) * F;
                float4 w00 = *(const float4*)(Wr + 0 * F);
                float4 w01 = *(const float4*)(Wr + 0 * F + 4);
                float4 w10 = *(const float4*)(Wr + 1 * F);
                float4 w11 = *(const float4*)(Wr + 1 * F + 4);
                float4 w20 = *(const float4*)(Wr + 2 * F);
                float4 w21 = *(const float4*)(Wr + 2 * F + 4);
                float4 w30 = *(const float4*)(Wr + 3 * F);
                float4 w31 = *(const float4*)(Wr + 3 * F + 4);

                #define ROWFMA(r, a) \
                    a0c[r].x += a.x * w00.x; a0c[r].y += a.x * w00.y; \
                    a0c[r].z += a.x * w00.z; a0c[r].w += a.x * w00.w; \
                    a1c[r].x += a.x * w01.x; a1c[r].y += a.x * w01.y; \
                    a1c[r].z += a.x * w01.z; a1c[r].w += a.x * w01.w; \
                    a0c[r].x += a.y * w10.x; a0c[r].y += a.y * w10.y; \
                    a0c[r].z += a.y * w10.z; a0c[r].w += a.y * w10.w; \
                    a1c[r].x += a.y * w11.x; a1c[r].y += a.y * w11.y; \
                    a1c[r].z += a.y * w11.z; a1c[r].w += a.y * w11.w; \
                    a0c[r].x += a.z * w20.x; a0c[r].y += a.z * w20.y; \
                    a0c[r].z += a.z * w20.z; a0c[r].w += a.z * w20.w; \
                    a1c[r].x += a.z * w21.x; a1c[r].y += a.z * w21.y; \
                    a1c[r].z += a.z * w21.z; a1c[r].w += a.z * w21.w; \
                    a0c[r].x += a.w * w30.x; a0c[r].y += a.w * w30.y; \
                    a0c[r].z += a.w * w30.z; a0c[r].w += a.w * w30.w; \
                    a1c[r].x += a.w * w31.x; a1c[r].y += a.w * w31.y; \
                    a1c[r].z += a.w * w31.z; a1c[r].w += a.w * w31.w;

                ROWFMA(0, a0)
                ROWFMA(1, a1)
                ROWFMA(2, a2)
                ROWFMA(3, a3)
                #undef ROWFMA
            }

            BAR_ARRIVE(3 + b);                      // signal empty (before stores)

            int row0 = t * TILE_ROWS + ri * 4;
            #pragma unroll
            for (int r = 0; r < 4; ++r) {
                int row = row0 + r;
                if (row < N_NODES) {
                    float4 v0 = a0c[r], v1 = a1c[r];
                    if (do_relu) {
                        v0.x = fmaxf(v0.x, 0.f); v0.y = fmaxf(v0.y, 0.f);
                        v0.z = fmaxf(v0.z, 0.f); v0.w = fmaxf(v0.w, 0.f);
                        v1.x = fmaxf(v1.x, 0.f); v1.y = fmaxf(v1.y, 0.f);
                        v1.z = fmaxf(v1.z, 0.f); v1.w = fmaxf(v1.w, 0.f);
                    }
                    float* op = hout + (size_t)row * F + ci * 8;
                    *(float4*)(op) = v0;
                    *(float4*)(op + 4) = v1;
                }
            }
        }
    }
}

// ---------------- launch ----------------
extern "C" void kernel_launch(void* const* d_in, const int* in_sizes, int n_in,
                              void* d_out, int out_size) {
    const float* x  = (const float*)d_in[0];
    const float* W1 = (const float*)d_in[1];
    const float* b1 = (const float*)d_in[2];
    const float* W2 = (const float*)d_in[3];
    const float* b2 = (const float*)d_in[4];
    const float* W3 = (const float*)d_in[5];
    const float* b3 = (const float*)d_in[6];
    const int* esrc = (const int*)d_in[7];
    const int* edst = (const int*)d_in[8];
    float* out = (float*)d_out;

    cudaFuncSetAttribute(k_layer, cudaFuncAttributeMaxDynamicSharedMemorySize,
                         SMEM_BYTES);

    void *ph0 = nullptr, *ph1 = nullptr;
    cudaGetSymbolAddress(&ph0, g_h0);
    cudaGetSymbolAddress(&ph1, g_h1);
    float* h0 = (float*)ph0;
    float* h1 = (float*)ph1;

    k_hist<<<(N_EDGES + 255) / 256, 256>>>(edst);
    k_scan1<<<1, 1024>>>();
    k_scatter<<<(N_EDGES + 255) / 256, 256>>>(esrc, edst);

    k_layer<<<LAYER_GRID, LAYER_THREADS, SMEM_BYTES>>>(x,  W1, b1, h0, 1);
    k_layer<<<LAYER_GRID, LAYER_THREADS, SMEM_BYTES>>>(h0, W2, b2, h1, 1);
    k_layer<<<LAYER_GRID, LAYER_THREADS, SMEM_BYTES>>>(h1, W3, b3, out, 0);
}

// round 13
// speedup vs baseline: 1.6088x; 1.6088x over previous
#include <cuda_runtime.h>
#include <cuda_bf16.h>
#include <cstdint>

#define N_NODES 100000
#define N_EDGES 1600000
#define F 128
#define TILE_ROWS 64
#define NTILES ((N_NODES + TILE_ROWS - 1) / TILE_ROWS)   // 1563
#define LAYER_GRID 148
#define LAYER_THREADS 512

// smem layout (bytes). Rows padded to 136 bf16 (272 B, 68 words ≡ 4 mod 32
// -> 8-row ldmatrix reads hit disjoint 4-bank groups: conflict-free).
#define RSTR 272
#define OFF_BIAS 0
#define OFF_WHI  512
#define OFF_WLO  (OFF_WHI + F * RSTR)          // 512 + 34816
#define OFF_T    (OFF_WLO + F * RSTR)          // 70144
#define TPLANE   (TILE_ROWS * RSTR)            // 17408
#define TBUF     (2 * TPLANE)                  // hi+lo per buffer
#define SMEM_BYTES (OFF_T + 2 * TBUF)          // 139776

// ---------------- PTX helpers ----------------
__device__ __forceinline__ uint32_t smem_u32(const void* p) {
    uint32_t a;
    asm("{ .reg .u64 t; cvta.to.shared.u64 t, %1; cvt.u32.u64 %0, t; }"
        : "=r"(a) : "l"(p));
    return a;
}
__device__ __forceinline__ void ldsm4(uint32_t* r, uint32_t addr) {
    asm volatile("ldmatrix.sync.aligned.m8n8.x4.shared.b16 {%0,%1,%2,%3}, [%4];"
                 : "=r"(r[0]), "=r"(r[1]), "=r"(r[2]), "=r"(r[3]) : "r"(addr));
}
__device__ __forceinline__ void ldsm4t(uint32_t* r, uint32_t addr) {
    asm volatile("ldmatrix.sync.aligned.m8n8.x4.trans.shared.b16 {%0,%1,%2,%3}, [%4];"
                 : "=r"(r[0]), "=r"(r[1]), "=r"(r[2]), "=r"(r[3]) : "r"(addr));
}
__device__ __forceinline__ void mma16816(float* d, const uint32_t* a,
                                         const uint32_t* b) {
    asm volatile(
        "mma.sync.aligned.m16n8k16.row.col.f32.bf16.bf16.f32 "
        "{%0,%1,%2,%3}, {%4,%5,%6,%7}, {%8,%9}, {%0,%1,%2,%3};"
        : "+f"(d[0]), "+f"(d[1]), "+f"(d[2]), "+f"(d[3])
        : "r"(a[0]), "r"(a[1]), "r"(a[2]), "r"(a[3]), "r"(b[0]), "r"(b[1]));
}

// ---------------- scratch (no allocations allowed) ----------------
__device__ int   g_counts[N_NODES];
__device__ int   g_off[N_NODES + 1];
__device__ int   g_cursor[N_NODES];
__device__ float g_inv[N_NODES];
__device__ int   g_csr[N_EDGES];
__device__ float g_h0[(size_t)N_NODES * F];
__device__ float g_h1[(size_t)N_NODES * F];

// ---------------- preprocessing: build CSR by dst (3 launches) ----------------
__global__ void k_hist(const int* __restrict__ dst) {
    int e = blockIdx.x * blockDim.x + threadIdx.x;
    if (e < N_EDGES) atomicAdd(&g_counts[dst[e]], 1);
}

__global__ void k_scan1() {
    __shared__ int wsum[32];
    __shared__ int base_sh;
    int tid = threadIdx.x;
    int lane = tid & 31;
    int wid = tid >> 5;
    if (tid == 0) base_sh = 0;
    __syncthreads();

    for (int base = 0; base < N_NODES; base += 4096) {
        int i = base + tid * 4;
        int4 v = make_int4(0, 0, 0, 0);
        if (i < N_NODES) v = *(const int4*)(g_counts + i);
        int s = v.x + v.y + v.z + v.w;

        int incl = s;
        #pragma unroll
        for (int d = 1; d < 32; d <<= 1) {
            int x = __shfl_up_sync(0xffffffffu, incl, d);
            if (lane >= d) incl += x;
        }
        if (lane == 31) wsum[wid] = incl;
        __syncthreads();

        if (wid == 0) {
            int ws = wsum[lane];
            int wincl = ws;
            #pragma unroll
            for (int d = 1; d < 32; d <<= 1) {
                int x = __shfl_up_sync(0xffffffffu, wincl, d);
                if (lane >= d) wincl += x;
            }
            wsum[lane] = wincl - ws;
        }
        __syncthreads();

        int chunk_base = base_sh;
        int pre = chunk_base + wsum[wid] + (incl - s);
        if (i < N_NODES) {
            int e0 = pre;
            int e1 = e0 + v.x;
            int e2 = e1 + v.y;
            int e3 = e2 + v.z;
            *(int4*)(g_off + i)    = make_int4(e0, e1, e2, e3);
            *(int4*)(g_cursor + i) = make_int4(e0, e1, e2, e3);
            g_inv[i + 0] = 1.0f / (float)(v.x > 0 ? v.x : 1);
            g_inv[i + 1] = 1.0f / (float)(v.y > 0 ? v.y : 1);
            g_inv[i + 2] = 1.0f / (float)(v.z > 0 ? v.z : 1);
            g_inv[i + 3] = 1.0f / (float)(v.w > 0 ? v.w : 1);
        }
        __syncthreads();
        if (tid == 1023) base_sh = chunk_base + wsum[31] + incl;
        __syncthreads();
    }
    if (tid == 0) g_off[N_NODES] = base_sh;
}

__global__ void k_scatter(const int* __restrict__ src, const int* __restrict__ dst) {
    int i = blockIdx.x * blockDim.x + threadIdx.x;
    if (i < N_EDGES) {
        int d = dst[i];
        int pos = atomicAdd(&g_cursor[d], 1);
        g_csr[pos] = src[i];
    }
    if (i < N_NODES) g_counts[i] = 0;   // re-zero for next invocation
}

// ---------------- fused layer: gather -> mma.sync bf16-split GEMM ----------------
// 64-row tiles, double-buffered bf16 hi/lo A-stage, parity-staggered warps:
// even warps [agg(next); mma(cur)], odd warps [mma(cur); agg(next)].
// One __syncthreads per tile.
__global__ __launch_bounds__(LAYER_THREADS, 1)
void k_layer(const float* __restrict__ hin, const float* __restrict__ Wg,
             const float* __restrict__ bias, float* __restrict__ hout,
             int do_relu) {
    extern __shared__ char smem[];
    uint32_t sbase = smem_u32(smem);
    float* sb = (float*)(smem + OFF_BIAS);

    int tid = threadIdx.x;
    int lane = tid & 31;
    int wId = tid >> 5;

    // stage W -> bf16 hi/lo planes [k][n], padded rows
    for (int idx = tid; idx < F * F; idx += LAYER_THREADS) {
        int k = idx >> 7;
        int n = idx & 127;
        float w = Wg[idx];
        __nv_bfloat16 h = __float2bfloat16_rn(w);
        __nv_bfloat16 l = __float2bfloat16_rn(w - __bfloat162float(h));
        *(__nv_bfloat16*)(smem + OFF_WHI + k * RSTR + n * 2) = h;
        *(__nv_bfloat16*)(smem + OFF_WLO + k * RSTR + n * 2) = l;
    }
    if (tid < F) sb[tid] = bias[tid];
    __syncthreads();

    // ---- gather + aggregate + bf16-split stage (4 rows per warp) ----
    auto agg = [&](int t, int buf) {
        uint32_t hi_off = OFF_T + buf * TBUF;
        uint32_t lo_off = hi_off + TPLANE;
        int lr0 = wId * 4;
        #pragma unroll 1
        for (int r = 0; r < 4; ++r) {
            int lr = lr0 + r;
            int row = t * TILE_ROWS + lr;
            float4 tv = make_float4(0.f, 0.f, 0.f, 0.f);
            if (row < N_NODES) {
                int e = g_off[row];
                int e1 = g_off[row + 1];
                float4 acc = make_float4(0.f, 0.f, 0.f, 0.f);
                for (; e + 4 <= e1; e += 4) {
                    int s0 = g_csr[e + 0], s1 = g_csr[e + 1];
                    int s2 = g_csr[e + 2], s3 = g_csr[e + 3];
                    float4 v0 = *(const float4*)(hin + (size_t)s0 * F + lane * 4);
                    float4 v1 = *(const float4*)(hin + (size_t)s1 * F + lane * 4);
                    float4 v2 = *(const float4*)(hin + (size_t)s2 * F + lane * 4);
                    float4 v3 = *(const float4*)(hin + (size_t)s3 * F + lane * 4);
                    acc.x += (v0.x + v1.x) + (v2.x + v3.x);
                    acc.y += (v0.y + v1.y) + (v2.y + v3.y);
                    acc.z += (v0.z + v1.z) + (v2.z + v3.z);
                    acc.w += (v0.w + v1.w) + (v2.w + v3.w);
                }
                for (; e < e1; ++e) {
                    int s = g_csr[e];
                    float4 v = *(const float4*)(hin + (size_t)s * F + lane * 4);
                    acc.x += v.x; acc.y += v.y; acc.z += v.z; acc.w += v.w;
                }
                float sc = g_inv[row];
                float4 hv = *(const float4*)(hin + (size_t)row * F + lane * 4);
                tv.x = fmaf(acc.x, sc, hv.x);
                tv.y = fmaf(acc.y, sc, hv.y);
                tv.z = fmaf(acc.z, sc, hv.z);
                tv.w = fmaf(acc.w, sc, hv.w);
            }
            __nv_bfloat16 h0 = __float2bfloat16_rn(tv.x);
            __nv_bfloat16 h1 = __float2bfloat16_rn(tv.y);
            __nv_bfloat16 h2 = __float2bfloat16_rn(tv.z);
            __nv_bfloat16 h3 = __float2bfloat16_rn(tv.w);
            __nv_bfloat16 l0 = __float2bfloat16_rn(tv.x - __bfloat162float(h0));
            __nv_bfloat16 l1 = __float2bfloat16_rn(tv.y - __bfloat162float(h1));
            __nv_bfloat16 l2 = __float2bfloat16_rn(tv.z - __bfloat162float(h2));
            __nv_bfloat16 l3 = __float2bfloat16_rn(tv.w - __bfloat162float(h3));
            __nv_bfloat162 ph01, ph23, pl01, pl23;
            ph01.x = h0; ph01.y = h1; ph23.x = h2; ph23.y = h3;
            pl01.x = l0; pl01.y = l1; pl23.x = l2; pl23.y = l3;
            uint32_t wo = lr * RSTR + lane * 8;
            *(uint2*)(smem + hi_off + wo) =
                make_uint2(*(uint32_t*)&ph01, *(uint32_t*)&ph23);
            *(uint2*)(smem + lo_off + wo) =
                make_uint2(*(uint32_t*)&pl01, *(uint32_t*)&pl23);
        }
    };

    // ---- mma + epilogue: warp computes rows [mt*16..+15] x cols [nb..nb+31] ----
    int mt = wId & 3;
    int nb = (wId >> 2) * 32;
    int grp = lane >> 3;
    int rr = lane & 7;
    // A ldmatrix lane addressing (x4): grp0=(r,k0) grp1=(r+8,k0) grp2=(r,k8) grp3=(r+8,k8)
    uint32_t a_lane_off = (uint32_t)((mt * 16 + rr + ((grp & 1) << 3)) * RSTR
                                     + ((grp & 2) ? 16 : 0));
    // B ldmatrix.trans lane addressing: rows k, 16-byte col chunks
    uint32_t b_lane_row = (uint32_t)((rr + ((grp & 1) << 3)) * RSTR
                                     + ((grp & 2) ? 16 : 0));

    auto mma_epi = [&](int t, int buf) {
        uint32_t Ahi = sbase + OFF_T + buf * TBUF + a_lane_off;
        uint32_t Alo = Ahi + TPLANE;
        uint32_t Bhi = sbase + OFF_WHI + b_lane_row + nb * 2;
        uint32_t Blo = sbase + OFF_WLO + b_lane_row + nb * 2;

        float acc[4][4];
        #pragma unroll
        for (int nt = 0; nt < 4; ++nt)
            #pragma unroll
            for (int j = 0; j < 4; ++j) acc[nt][j] = 0.f;

        #pragma unroll 1
        for (int kt = 0; kt < 8; ++kt) {
            uint32_t ah[4], al[4], bh[8], bl[8];
            ldsm4(ah, Ahi + kt * 32);
            ldsm4(al, Alo + kt * 32);
            ldsm4t(bh + 0, Bhi + kt * 16 * RSTR);
            ldsm4t(bh + 4, Bhi + kt * 16 * RSTR + 32);
            ldsm4t(bl + 0, Blo + kt * 16 * RSTR);
            ldsm4t(bl + 4, Blo + kt * 16 * RSTR + 32);
            #pragma unroll
            for (int nt = 0; nt < 4; ++nt) mma16816(acc[nt], ah, bh + nt * 2);
            #pragma unroll
            for (int nt = 0; nt < 4; ++nt) mma16816(acc[nt], al, bh + nt * 2);
            #pragma unroll
            for (int nt = 0; nt < 4; ++nt) mma16816(acc[nt], ah, bl + nt * 2);
        }

        int row0 = t * TILE_ROWS + mt * 16 + (lane >> 2);
        int colb = (lane & 3) * 2;
        #pragma unroll
        for (int nt = 0; nt < 4; ++nt) {
            int col = nb + nt * 8 + colb;
            float2 bb = *(const float2*)(sb + col);
            float v0 = acc[nt][0] + bb.x;
            float v1 = acc[nt][1] + bb.y;
            float v2 = acc[nt][2] + bb.x;
            float v3 = acc[nt][3] + bb.y;
            if (do_relu) {
                v0 = fmaxf(v0, 0.f); v1 = fmaxf(v1, 0.f);
                v2 = fmaxf(v2, 0.f); v3 = fmaxf(v3, 0.f);
            }
            if (row0 < N_NODES)
                *(float2*)(hout + (size_t)row0 * F + col) = make_float2(v0, v1);
            if (row0 + 8 < N_NODES)
                *(float2*)(hout + (size_t)(row0 + 8) * F + col) = make_float2(v2, v3);
        }
    };

    // ---- depth-2 pipeline, parity stagger, one syncthreads per tile ----
    int odd = wId & 1;
    int t = blockIdx.x;
    agg(t, 0);
    int prev = t;
    int si = 1;
    for (t += gridDim.x; t < NTILES; t += gridDim.x, ++si) {
        __syncthreads();
        int sbuf = si & 1;
        int cbuf = sbuf ^ 1;
        if (odd) {
            mma_epi(prev, cbuf);
            agg(t, sbuf);
        } else {
            agg(t, sbuf);
            mma_epi(prev, cbuf);
        }
        prev = t;
    }
    __syncthreads();
    mma_epi(prev, (si & 1) ^ 1);
}

// ---------------- launch ----------------
extern "C" void kernel_launch(void* const* d_in, const int* in_sizes, int n_in,
                              void* d_out, int out_size) {
    const float* x  = (const float*)d_in[0];
    const float* W1 = (const float*)d_in[1];
    const float* b1 = (const float*)d_in[2];
    const float* W2 = (const float*)d_in[3];
    const float* b2 = (const float*)d_in[4];
    const float* W3 = (const float*)d_in[5];
    const float* b3 = (const float*)d_in[6];
    const int* esrc = (const int*)d_in[7];
    const int* edst = (const int*)d_in[8];
    float* out = (float*)d_out;

    cudaFuncSetAttribute(k_layer, cudaFuncAttributeMaxDynamicSharedMemorySize,
                         SMEM_BYTES);

    void *ph0 = nullptr, *ph1 = nullptr;
    cudaGetSymbolAddress(&ph0, g_h0);
    cudaGetSymbolAddress(&ph1, g_h1);
    float* h0 = (float*)ph0;
    float* h1 = (float*)ph1;

    k_hist<<<(N_EDGES + 255) / 256, 256>>>(edst);
    k_scan1<<<1, 1024>>>();
    k_scatter<<<(N_EDGES + 255) / 256, 256>>>(esrc, edst);

    k_layer<<<LAYER_GRID, LAYER_THREADS, SMEM_BYTES>>>(x,  W1, b1, h0, 1);
    k_layer<<<LAYER_GRID, LAYER_THREADS, SMEM_BYTES>>>(h0, W2, b2, h1, 1);
    k_layer<<<LAYER_GRID, LAYER_THREADS, SMEM_BYTES>>>(h1, W3, b3, out, 0);
}

// round 14
// speedup vs baseline: 2.0497x; 1.2741x over previous
#include <cuda_runtime.h>
#include <cuda_bf16.h>
#include <cstdint>

#define N_NODES 100000
#define N_EDGES 1600000
#define F 128
#define TILE_ROWS 64
#define NTILES ((N_NODES + TILE_ROWS - 1) / TILE_ROWS)   // 1563
#define LAYER_GRID 148
#define LAYER_THREADS 1024

// smem layout (bytes). Rows padded to 136 bf16 (272 B, 68 words ≡ 4 mod 32
// -> 8-row ldmatrix reads hit disjoint 4-bank groups: conflict-free).
#define RSTR 272
#define OFF_BIAS 0
#define OFF_WHI  512
#define OFF_WLO  (OFF_WHI + F * RSTR)          // 512 + 34816
#define OFF_T    (OFF_WLO + F * RSTR)          // 70144
#define TPLANE   (TILE_ROWS * RSTR)            // 17408
#define TBUF     (2 * TPLANE)                  // hi+lo per buffer
#define SMEM_BYTES (OFF_T + 2 * TBUF)          // 139776

// ---------------- PTX helpers ----------------
__device__ __forceinline__ uint32_t smem_u32(const void* p) {
    uint32_t a;
    asm("{ .reg .u64 t; cvta.to.shared.u64 t, %1; cvt.u32.u64 %0, t; }"
        : "=r"(a) : "l"(p));
    return a;
}
__device__ __forceinline__ void ldsm4(uint32_t* r, uint32_t addr) {
    asm volatile("ldmatrix.sync.aligned.m8n8.x4.shared.b16 {%0,%1,%2,%3}, [%4];"
                 : "=r"(r[0]), "=r"(r[1]), "=r"(r[2]), "=r"(r[3]) : "r"(addr));
}
__device__ __forceinline__ void ldsm4t(uint32_t* r, uint32_t addr) {
    asm volatile("ldmatrix.sync.aligned.m8n8.x4.trans.shared.b16 {%0,%1,%2,%3}, [%4];"
                 : "=r"(r[0]), "=r"(r[1]), "=r"(r[2]), "=r"(r[3]) : "r"(addr));
}
__device__ __forceinline__ void mma16816(float* d, const uint32_t* a,
                                         const uint32_t* b) {
    asm volatile(
        "mma.sync.aligned.m16n8k16.row.col.f32.bf16.bf16.f32 "
        "{%0,%1,%2,%3}, {%4,%5,%6,%7}, {%8,%9}, {%0,%1,%2,%3};"
        : "+f"(d[0]), "+f"(d[1]), "+f"(d[2]), "+f"(d[3])
        : "r"(a[0]), "r"(a[1]), "r"(a[2]), "r"(a[3]), "r"(b[0]), "r"(b[1]));
}

// ---------------- scratch (no allocations allowed) ----------------
__device__ int   g_counts[N_NODES];
__device__ int   g_off[N_NODES + 1];
__device__ int   g_cursor[N_NODES];
__device__ float g_inv[N_NODES];
__device__ int   g_csr[N_EDGES];
__device__ float g_h0[(size_t)N_NODES * F];
__device__ float g_h1[(size_t)N_NODES * F];

// ---------------- preprocessing: build CSR by dst (3 launches) ----------------
__global__ void k_hist(const int4* __restrict__ dst4) {
    int i = blockIdx.x * blockDim.x + threadIdx.x;
    if (i < N_EDGES / 4) {
        int4 d = dst4[i];
        atomicAdd(&g_counts[d.x], 1);
        atomicAdd(&g_counts[d.y], 1);
        atomicAdd(&g_counts[d.z], 1);
        atomicAdd(&g_counts[d.w], 1);
    }
}

__global__ void k_scan1() {
    __shared__ int wsum[32];
    __shared__ int base_sh;
    int tid = threadIdx.x;
    int lane = tid & 31;
    int wid = tid >> 5;
    if (tid == 0) base_sh = 0;
    __syncthreads();

    for (int base = 0; base < N_NODES; base += 4096) {
        int i = base + tid * 4;
        int4 v = make_int4(0, 0, 0, 0);
        if (i < N_NODES) v = *(const int4*)(g_counts + i);
        int s = v.x + v.y + v.z + v.w;

        int incl = s;
        #pragma unroll
        for (int d = 1; d < 32; d <<= 1) {
            int x = __shfl_up_sync(0xffffffffu, incl, d);
            if (lane >= d) incl += x;
        }
        if (lane == 31) wsum[wid] = incl;
        __syncthreads();

        if (wid == 0) {
            int ws = wsum[lane];
            int wincl = ws;
            #pragma unroll
            for (int d = 1; d < 32; d <<= 1) {
                int x = __shfl_up_sync(0xffffffffu, wincl, d);
                if (lane >= d) wincl += x;
            }
            wsum[lane] = wincl - ws;
        }
        __syncthreads();

        int chunk_base = base_sh;
        int pre = chunk_base + wsum[wid] + (incl - s);
        if (i < N_NODES) {
            int e0 = pre;
            int e1 = e0 + v.x;
            int e2 = e1 + v.y;
            int e3 = e2 + v.z;
            *(int4*)(g_off + i)    = make_int4(e0, e1, e2, e3);
            *(int4*)(g_cursor + i) = make_int4(e0, e1, e2, e3);
            g_inv[i + 0] = 1.0f / (float)(v.x > 0 ? v.x : 1);
            g_inv[i + 1] = 1.0f / (float)(v.y > 0 ? v.y : 1);
            g_inv[i + 2] = 1.0f / (float)(v.z > 0 ? v.z : 1);
            g_inv[i + 3] = 1.0f / (float)(v.w > 0 ? v.w : 1);
        }
        __syncthreads();
        if (tid == 1023) base_sh = chunk_base + wsum[31] + incl;
        __syncthreads();
    }
    if (tid == 0) g_off[N_NODES] = base_sh;
}

__global__ void k_scatter(const int* __restrict__ src, const int* __restrict__ dst) {
    int i = blockIdx.x * blockDim.x + threadIdx.x;
    if (i < N_EDGES) {
        int d = dst[i];
        int pos = atomicAdd(&g_cursor[d], 1);
        g_csr[pos] = src[i];
    }
    if (i < N_NODES) g_counts[i] = 0;   // re-zero for next invocation
}

// ---------------- fused layer: gather -> mma.sync bf16-split GEMM ----------------
// 1024 threads (32 warps) per CTA, 1 CTA/SM persistent.
// 64-row tiles, double-buffered bf16 hi/lo A-stage, parity-staggered warps.
__global__ __launch_bounds__(LAYER_THREADS, 1)
void k_layer(const float* __restrict__ hin, const float* __restrict__ Wg,
             const float* __restrict__ bias, float* __restrict__ hout,
             int do_relu) {
    extern __shared__ char smem[];
    uint32_t sbase = smem_u32(smem);
    float* sb = (float*)(smem + OFF_BIAS);

    int tid = threadIdx.x;
    int lane = tid & 31;
    int wId = tid >> 5;

    // stage W -> bf16 hi/lo planes [k][n], padded rows
    for (int idx = tid; idx < F * F; idx += LAYER_THREADS) {
        int k = idx >> 7;
        int n = idx & 127;
        float w = Wg[idx];
        __nv_bfloat16 h = __float2bfloat16_rn(w);
        __nv_bfloat16 l = __float2bfloat16_rn(w - __bfloat162float(h));
        *(__nv_bfloat16*)(smem + OFF_WHI + k * RSTR + n * 2) = h;
        *(__nv_bfloat16*)(smem + OFF_WLO + k * RSTR + n * 2) = l;
    }
    if (tid < F) sb[tid] = bias[tid];
    __syncthreads();

    // ---- gather + aggregate + bf16-split stage (2 rows per warp) ----
    auto agg = [&](int t, int buf) {
        uint32_t hi_off = OFF_T + buf * TBUF;
        uint32_t lo_off = hi_off + TPLANE;
        int lr0 = wId * 2;
        #pragma unroll 1
        for (int r = 0; r < 2; ++r) {
            int lr = lr0 + r;
            int row = t * TILE_ROWS + lr;
            float4 tv = make_float4(0.f, 0.f, 0.f, 0.f);
            if (row < N_NODES) {
                int e = g_off[row];
                int e1 = g_off[row + 1];
                float4 acc = make_float4(0.f, 0.f, 0.f, 0.f);
                for (; e + 4 <= e1; e += 4) {
                    int s0 = g_csr[e + 0], s1 = g_csr[e + 1];
                    int s2 = g_csr[e + 2], s3 = g_csr[e + 3];
                    float4 v0 = *(const float4*)(hin + (size_t)s0 * F + lane * 4);
                    float4 v1 = *(const float4*)(hin + (size_t)s1 * F + lane * 4);
                    float4 v2 = *(const float4*)(hin + (size_t)s2 * F + lane * 4);
                    float4 v3 = *(const float4*)(hin + (size_t)s3 * F + lane * 4);
                    acc.x += (v0.x + v1.x) + (v2.x + v3.x);
                    acc.y += (v0.y + v1.y) + (v2.y + v3.y);
                    acc.z += (v0.z + v1.z) + (v2.z + v3.z);
                    acc.w += (v0.w + v1.w) + (v2.w + v3.w);
                }
                for (; e < e1; ++e) {
                    int s = g_csr[e];
                    float4 v = *(const float4*)(hin + (size_t)s * F + lane * 4);
                    acc.x += v.x; acc.y += v.y; acc.z += v.z; acc.w += v.w;
                }
                float sc = g_inv[row];
                float4 hv = *(const float4*)(hin + (size_t)row * F + lane * 4);
                tv.x = fmaf(acc.x, sc, hv.x);
                tv.y = fmaf(acc.y, sc, hv.y);
                tv.z = fmaf(acc.z, sc, hv.z);
                tv.w = fmaf(acc.w, sc, hv.w);
            }
            __nv_bfloat16 h0 = __float2bfloat16_rn(tv.x);
            __nv_bfloat16 h1 = __float2bfloat16_rn(tv.y);
            __nv_bfloat16 h2 = __float2bfloat16_rn(tv.z);
            __nv_bfloat16 h3 = __float2bfloat16_rn(tv.w);
            __nv_bfloat16 l0 = __float2bfloat16_rn(tv.x - __bfloat162float(h0));
            __nv_bfloat16 l1 = __float2bfloat16_rn(tv.y - __bfloat162float(h1));
            __nv_bfloat16 l2 = __float2bfloat16_rn(tv.z - __bfloat162float(h2));
            __nv_bfloat16 l3 = __float2bfloat16_rn(tv.w - __bfloat162float(h3));
            __nv_bfloat162 ph01, ph23, pl01, pl23;
            ph01.x = h0; ph01.y = h1; ph23.x = h2; ph23.y = h3;
            pl01.x = l0; pl01.y = l1; pl23.x = l2; pl23.y = l3;
            uint32_t wo = lr * RSTR + lane * 8;
            *(uint2*)(smem + hi_off + wo) =
                make_uint2(*(uint32_t*)&ph01, *(uint32_t*)&ph23);
            *(uint2*)(smem + lo_off + wo) =
                make_uint2(*(uint32_t*)&pl01, *(uint32_t*)&pl23);
        }
    };

    // ---- mma + epilogue: warp computes rows [mt*16..+15] x cols [nb..nb+15] ----
    int mt = wId & 3;
    int nb = (wId >> 2) * 16;
    int grp = lane >> 3;
    int rr = lane & 7;
    // A ldmatrix lane addressing (x4): grp0=(r,k0) grp1=(r+8,k0) grp2=(r,k8) grp3=(r+8,k8)
    uint32_t a_lane_off = (uint32_t)((mt * 16 + rr + ((grp & 1) << 3)) * RSTR
                                     + ((grp & 2) ? 16 : 0));
    // B ldmatrix.trans lane addressing: rows k, 16-byte col chunks
    uint32_t b_lane_row = (uint32_t)((rr + ((grp & 1) << 3)) * RSTR
                                     + ((grp & 2) ? 16 : 0));

    auto mma_epi = [&](int t, int buf) {
        uint32_t Ahi = sbase + OFF_T + buf * TBUF + a_lane_off;
        uint32_t Alo = Ahi + TPLANE;
        uint32_t Bhi = sbase + OFF_WHI + b_lane_row + nb * 2;
        uint32_t Blo = sbase + OFF_WLO + b_lane_row + nb * 2;

        float acc[2][4];
        #pragma unroll
        for (int nt = 0; nt < 2; ++nt)
            #pragma unroll
            for (int j = 0; j < 4; ++j) acc[nt][j] = 0.f;

        #pragma unroll 1
        for (int kt = 0; kt < 8; ++kt) {
            uint32_t ah[4], al[4], bh[4], bl[4];
            ldsm4(ah, Ahi + kt * 32);
            ldsm4(al, Alo + kt * 32);
            ldsm4t(bh, Bhi + kt * 16 * RSTR);
            ldsm4t(bl, Blo + kt * 16 * RSTR);
            #pragma unroll
            for (int nt = 0; nt < 2; ++nt) mma16816(acc[nt], ah, bh + nt * 2);
            #pragma unroll
            for (int nt = 0; nt < 2; ++nt) mma16816(acc[nt], al, bh + nt * 2);
            #pragma unroll
            for (int nt = 0; nt < 2; ++nt) mma16816(acc[nt], ah, bl + nt * 2);
        }

        int row0 = t * TILE_ROWS + mt * 16 + (lane >> 2);
        int colb = (lane & 3) * 2;
        #pragma unroll
        for (int nt = 0; nt < 2; ++nt) {
            int col = nb + nt * 8 + colb;
            float2 bb = *(const float2*)(sb + col);
            float v0 = acc[nt][0] + bb.x;
            float v1 = acc[nt][1] + bb.y;
            float v2 = acc[nt][2] + bb.x;
            float v3 = acc[nt][3] + bb.y;
            if (do_relu) {
                v0 = fmaxf(v0, 0.f); v1 = fmaxf(v1, 0.f);
                v2 = fmaxf(v2, 0.f); v3 = fmaxf(v3, 0.f);
            }
            if (row0 < N_NODES)
                *(float2*)(hout + (size_t)row0 * F + col) = make_float2(v0, v1);
            if (row0 + 8 < N_NODES)
                *(float2*)(hout + (size_t)(row0 + 8) * F + col) = make_float2(v2, v3);
        }
    };

    // ---- depth-2 pipeline, parity stagger, one syncthreads per tile ----
    int odd = wId & 1;
    int t = blockIdx.x;
    agg(t, 0);
    int prev = t;
    int si = 1;
    for (t += gridDim.x; t < NTILES; t += gridDim.x, ++si) {
        __syncthreads();
        int sbuf = si & 1;
        int cbuf = sbuf ^ 1;
        if (odd) {
            mma_epi(prev, cbuf);
            agg(t, sbuf);
        } else {
            agg(t, sbuf);
            mma_epi(prev, cbuf);
        }
        prev = t;
    }
    __syncthreads();
    mma_epi(prev, (si & 1) ^ 1);
}

// ---------------- launch ----------------
extern "C" void kernel_launch(void* const* d_in, const int* in_sizes, int n_in,
                              void* d_out, int out_size) {
    const float* x  = (const float*)d_in[0];
    const float* W1 = (const float*)d_in[1];
    const float* b1 = (const float*)d_in[2];
    const float* W2 = (const float*)d_in[3];
    const float* b2 = (const float*)d_in[4];
    const float* W3 = (const float*)d_in[5];
    const float* b3 = (const float*)d_in[6];
    const int* esrc = (const int*)d_in[7];
    const int* edst = (const int*)d_in[8];
    float* out = (float*)d_out;

    cudaFuncSetAttribute(k_layer, cudaFuncAttributeMaxDynamicSharedMemorySize,
                         SMEM_BYTES);

    void *ph0 = nullptr, *ph1 = nullptr;
    cudaGetSymbolAddress(&ph0, g_h0);
    cudaGetSymbolAddress(&ph1, g_h1);
    float* h0 = (float*)ph0;
    float* h1 = (float*)ph1;

    k_hist<<<(N_EDGES / 4 + 255) / 256, 256>>>((const int4*)edst);
    k_scan1<<<1, 1024>>>();
    k_scatter<<<(N_EDGES + 255) / 256, 256>>>(esrc, edst);

    k_layer<<<LAYER_GRID, LAYER_THREADS, SMEM_BYTES>>>(x,  W1, b1, h0, 1);
    k_layer<<<LAYER_GRID, LAYER_THREADS, SMEM_BYTES>>>(h0, W2, b2, h1, 1);
    k_layer<<<LAYER_GRID, LAYER_THREADS, SMEM_BYTES>>>(h1, W3, b3, out, 0);
}